// round 17
// baseline (speedup 1.0000x reference)
#include <cuda_runtime.h>
#include <cuda_fp16.h>
#include <cstdint>
#include <cstddef>

#define BB 2
#define SS 2048
#define DD 4096
#define HH 32
#define HD 128
#define NEG_INF -1000000000.0f

#define NELT ((size_t)BB * SS * DD)          // 16,777,216
#define NP   ((size_t)BB * HH * SS * SS)     // 268,435,456

// ---------------- scratch (device globals; alloc APIs forbidden) ----------
__device__ __half g_hh[NELT];                 // hidden hi
__device__ __half g_qkh[NELT];                // Wqk hi
__device__ __half g_vh[NELT];                 // Wv hi
__device__ __half g_oh[NELT];                 // Wo hi
__device__ __half g_qh[NELT];                 // roped Q hi (b,s,h,hd)
__device__ __half g_kh[NELT];                 // roped K hi (b,s,h,hd)
__device__ __half g_vth[NELT];                // V^T hi (b,h,d,k)
__device__ __half g_aoh[NELT];                // attn-out gathered fp16
__device__ __half g_ph[NP];                   // softmax P fp16

// ---------------- helpers ---------------------------------------------------
__device__ __forceinline__ uint32_t smem_u32(const void* p) {
    uint32_t a;
    asm("{ .reg .u64 t; cvta.to.shared.u64 t, %1; cvt.u32.u64 %0, t; }" : "=r"(a) : "l"(p));
    return a;
}
__device__ __forceinline__ void cp_async16(uint32_t dst, const void* src) {
    asm volatile("cp.async.cg.shared.global [%0], [%1], 16;" :: "r"(dst), "l"(src));
}
#define CP_COMMIT() asm volatile("cp.async.commit_group;" ::: "memory")
#define CP_WAIT0()  asm volatile("cp.async.wait_group 0;" ::: "memory")
#define CP_WAIT1()  asm volatile("cp.async.wait_group 1;" ::: "memory")

__device__ __forceinline__ void ldmx4(uint32_t* r, uint32_t addr) {
    asm volatile("ldmatrix.sync.aligned.m8n8.x4.shared.b16 {%0,%1,%2,%3}, [%4];"
                 : "=r"(r[0]), "=r"(r[1]), "=r"(r[2]), "=r"(r[3]) : "r"(addr));
}
__device__ __forceinline__ void mma16816(float* d, const uint32_t* a, const uint32_t* b) {
    asm volatile(
        "mma.sync.aligned.m16n8k16.row.col.f32.f16.f16.f32 "
        "{%0,%1,%2,%3}, {%4,%5,%6,%7}, {%8,%9}, {%0,%1,%2,%3};"
        : "+f"(d[0]), "+f"(d[1]), "+f"(d[2]), "+f"(d[3])
        : "r"(a[0]), "r"(a[1]), "r"(a[2]), "r"(a[3]), "r"(b[0]), "r"(b[1]));
}

// ---- BK=64 tiles ------------------------------------------------------------
#define TILE64 16384                    // 128 rows x 128B (64 fp16)
#define STG (2 * TILE64)                // 2 tiles (A, B) per stage = 32KB
#define NST 3
#define SMEM_P (NST * STG)              // 98304 (gemm / pv)
#define SMEM_S (2 * STG)                // 65536 (score: HD fits in 2 stages)

// swizzled byte offset within a 128x64-fp16 tile (128B rows); chunk 0..7
__device__ __forceinline__ uint32_t sw64(int r, int chunk) {
    return (uint32_t)(r << 7) + (((chunk ^ (r & 7)) << 4));
}

// ---- 1-product K=16 MMA step within a BK=64 stage; ks in 0..3 ---------------
__device__ __forceinline__ void hmma64(
    uint32_t sb, int ks, int wm, int wn, int lr, int lc, float (&acc)[4][4][4])
{
    const int chunk = ks * 2 + lc;
    uint32_t bh[4][2];
#pragma unroll
    for (int g = 0; g < 2; g++) {
        int r = wn + g * 16 + lr;
        uint32_t rb[4];
        ldmx4(rb, sb + TILE64 + sw64(r, chunk));
        bh[g*2+0][0] = rb[0]; bh[g*2+0][1] = rb[2];
        bh[g*2+1][0] = rb[1]; bh[g*2+1][1] = rb[3];
    }
#pragma unroll
    for (int mi = 0; mi < 4; mi++) {
        int r = wm + mi * 16 + lr;
        uint32_t ah[4];
        ldmx4(ah, sb + sw64(r, chunk));
#pragma unroll
        for (int ni = 0; ni < 4; ni++)
            mma16816(acc[mi][ni], ah, bh[ni]);
    }
}

// stage loader: 2 tiles of 128x64 fp16, 2048 cp.async over 256 threads
__device__ __forceinline__ void load_stage64(
    uint32_t db, const __half* base0, const __half* base1, int ld, int kc, int t)
{
#pragma unroll
    for (int i = 0; i < 8; i++) {
        int idx = t + (i << 8);              // 0..2047
        int tile = idx >> 10;                // 0..1
        int w = idx & 1023;
        int r = w >> 3, c = w & 7;
        const __half* src = (tile == 0 ? base0 : base1)
                            + (size_t)r * ld + kc + (c << 3);
        cp_async16(db + tile * TILE64 + sw64(r, c), src);
    }
    CP_COMMIT();
}

// ---------------------------------------------------------------------------
// gemm_qkv_tc: fused QK + V projections (blockIdx.z selects), fp16 1-product,
// BK=64, 3-stage, one barrier/iter. z=0: bias+RoPE -> K hi. z=1: bias+transpose.
// ---------------------------------------------------------------------------
__global__ __launch_bounds__(256, 2) void gemm_qkv_tc(
    const __half* __restrict__ Ah,
    const __half* __restrict__ Wqk, const __half* __restrict__ Wv,
    const float* __restrict__ bqk, const float* __restrict__ bv,
    const float* __restrict__ cosp, const float* __restrict__ sinp,
    __half* __restrict__ Kh, __half* __restrict__ Vth)
{
    extern __shared__ char smem[];
    const uint32_t sbase = smem_u32(smem);
    const int t = threadIdx.x;
    const int wid = t >> 5, lane = t & 31;
    const int bm = blockIdx.y << 7, bn = blockIdx.x << 7;
    const int zv = blockIdx.z;               // 0 = QK, 1 = V

    const __half* base0 = Ah + (size_t)bm * DD;
    const __half* base1 = (zv ? Wv : Wqk) + (size_t)bn * DD;
    const float* bias = zv ? bv : bqk;

    load_stage64(sbase,       base0, base1, DD, 0,  t);
    load_stage64(sbase + STG, base0, base1, DD, 64, t);

    const int wm = (wid & 1) << 6;
    const int wn = (wid >> 1) << 5;
    const int lr = lane & 15, lc = lane >> 4;
    float acc[4][4][4] = {};
    const int iters = DD / 64;     // 64

    for (int it = 0; it < iters; it++) {
        int stg = it % NST;
        CP_WAIT1();
        __syncthreads();
        uint32_t sb = sbase + stg * STG;
        hmma64(sb, 0, wm, wn, lr, lc, acc);
        hmma64(sb, 1, wm, wn, lr, lc, acc);
        hmma64(sb, 2, wm, wn, lr, lc, acc);
        hmma64(sb, 3, wm, wn, lr, lc, acc);
        int nx = it + 2;
        if (nx < iters) load_stage64(sbase + (nx % NST) * STG, base0, base1, DD, nx * 64, t);
        else CP_COMMIT();
    }

    const int qr = lane >> 2, qc = (lane & 3) << 1;

    // stage acc (+bias) into padded fp32 smem tile
    __syncthreads();
    const int PAD = zv ? 133 : 132;
    float* eps = (float*)smem;
#pragma unroll
    for (int mi = 0; mi < 4; mi++) {
#pragma unroll
        for (int ni = 0; ni < 4; ni++) {
            int cl = wn + ni * 8 + qc;
            float b0 = bias[bn + cl];
            float b1 = bias[bn + cl + 1];
            int r0 = wm + mi * 16 + qr;
            eps[r0 * PAD + cl]           = acc[mi][ni][0] + b0;
            eps[r0 * PAD + cl + 1]       = acc[mi][ni][1] + b1;
            eps[(r0 + 8) * PAD + cl]     = acc[mi][ni][2] + b0;
            eps[(r0 + 8) * PAD + cl + 1] = acc[mi][ni][3] + b1;
        }
    }
    __syncthreads();

    if (!zv) {
        // RoPE within the head tile (N-tile == one head): pairs (d, d+64)
#pragma unroll
        for (int q8 = 0; q8 < 32; q8++) {
            int idx = t + (q8 << 8);          // 0..8191
            int d = idx & 63, r = idx >> 6;
            int m = bm + r;
            size_t cb = (size_t)m * HD;
            float c0 = cosp[cb + d],      s0 = sinp[cb + d];
            float c1 = cosp[cb + d + 64], s1 = sinp[cb + d + 64];
            float x0 = eps[r * 132 + d], x1 = eps[r * 132 + d + 64];
            float y0 = x0 * c0 - x1 * s0;
            float y1 = x1 * c1 + x0 * s1;
            size_t o = (size_t)m * DD + bn + d;
            Kh[o]      = __float2half_rn(y0);
            Kh[o + 64] = __float2half_rn(y1);
        }
    } else {
        // transpose tile (s x d) -> Vt (b,h,d,s) fp16 hi
        int bh = ((bm >> 11) << 5) + (bn >> 7);
        int sbase_g = bm & (SS - 1);
#pragma unroll
        for (int q8 = 0; q8 < 16; q8++) {
            int qi = t + (q8 << 8);           // 0..4095 quads
            int d = qi >> 5;
            int sq = (qi & 31) << 2;
            float f0 = eps[(sq + 0) * 133 + d];
            float f1 = eps[(sq + 1) * 133 + d];
            float f2 = eps[(sq + 2) * 133 + d];
            float f3 = eps[(sq + 3) * 133 + d];
            size_t o = ((size_t)bh * HD + d) * SS + sbase_g + sq;
            *(__half2*)&Vth[o]     = __halves2half2(__float2half_rn(f0), __float2half_rn(f1));
            *(__half2*)&Vth[o + 2] = __halves2half2(__float2half_rn(f2), __float2half_rn(f3));
        }
    }
}

// ---------------------------------------------------------------------------
// gemm1_tc: final projection, fp16 1-product, fp32 out. BK=64, 3-stage.
// ---------------------------------------------------------------------------
__global__ __launch_bounds__(256, 2) void gemm1_tc(
    const __half* __restrict__ Ah, const __half* __restrict__ Bh,
    float* __restrict__ C)
{
    extern __shared__ char smem[];
    const uint32_t sbase = smem_u32(smem);
    const int t = threadIdx.x;
    const int wid = t >> 5, lane = t & 31;
    const int bm = blockIdx.y << 7, bn = blockIdx.x << 7;

    const __half* base0 = Ah + (size_t)bm * DD;
    const __half* base1 = Bh + (size_t)bn * DD;

    load_stage64(sbase,       base0, base1, DD, 0,  t);
    load_stage64(sbase + STG, base0, base1, DD, 64, t);

    const int wm = (wid & 1) << 6;
    const int wn = (wid >> 1) << 5;
    const int lr = lane & 15, lc = lane >> 4;
    float acc[4][4][4] = {};
    const int iters = DD / 64;

    for (int it = 0; it < iters; it++) {
        int stg = it % NST;
        CP_WAIT1();
        __syncthreads();
        uint32_t sb = sbase + stg * STG;
        hmma64(sb, 0, wm, wn, lr, lc, acc);
        hmma64(sb, 1, wm, wn, lr, lc, acc);
        hmma64(sb, 2, wm, wn, lr, lc, acc);
        hmma64(sb, 3, wm, wn, lr, lc, acc);
        int nx = it + 2;
        if (nx < iters) load_stage64(sbase + (nx % NST) * STG, base0, base1, DD, nx * 64, t);
        else CP_COMMIT();
    }

    const int qr = lane >> 2, qc = (lane & 3) << 1;
#pragma unroll
    for (int mi = 0; mi < 4; mi++) {
#pragma unroll
        for (int ni = 0; ni < 4; ni++) {
            int col = bn + wn + ni * 8 + qc;
            int row0 = bm + wm + mi * 16 + qr;
            float2 v0 = { acc[mi][ni][0], acc[mi][ni][1] };
            float2 v1 = { acc[mi][ni][2], acc[mi][ni][3] };
            *(float2*)&C[(size_t)row0 * DD + col] = v0;
            *(float2*)&C[(size_t)(row0 + 8) * DD + col] = v1;
        }
    }
}

// ---------------------------------------------------------------------------
// score_tc: P = Qh.Kh (fp16 1-product), causal. HD=128 fully preloaded:
// one wait + one barrier, then 8 uninterrupted MMA chunks.
// Above-diagonal tiles write fp32 zeros; softmax writes only causal region.
// ---------------------------------------------------------------------------
__global__ __launch_bounds__(256, 2) void score_tc(
    const __half* __restrict__ Qh, const __half* __restrict__ Kh,
    float* __restrict__ P)
{
    extern __shared__ char smem[];
    const int q0 = blockIdx.y << 7, k0 = blockIdx.x << 7;
    const int bh = blockIdx.z;
    const size_t pbase = ((size_t)bh * SS + q0) * SS + k0;
    const int t = threadIdx.x;

    if (k0 > q0) {                 // fully-masked tile -> exact zeros
        const float4 z = { 0.f, 0.f, 0.f, 0.f };
#pragma unroll
        for (int q8 = 0; q8 < 16; q8++) {
            int i = t + (q8 << 8);
            int r = i >> 5, c4 = (i & 31) << 2;
            *(float4*)&P[pbase + (size_t)r * SS + c4] = z;
        }
        return;
    }

    const int b = bh >> 5, h = bh & 31;
    const uint32_t sbase = smem_u32(smem);
    const int wid = t >> 5, lane = t & 31;

    const __half* base0 = Qh + (size_t)(b * SS + q0) * DD + (h << 7);
    const __half* base1 = Kh + (size_t)(b * SS + k0) * DD + (h << 7);

    load_stage64(sbase,       base0, base1, DD, 0,  t);
    load_stage64(sbase + STG, base0, base1, DD, 64, t);
    CP_WAIT0();
    __syncthreads();

    const int wm = (wid & 1) << 6;
    const int wn = (wid >> 1) << 5;
    const int lr = lane & 15, lc = lane >> 4;
    float acc[4][4][4] = {};

#pragma unroll
    for (int st = 0; st < 2; st++) {
        uint32_t sb = sbase + st * STG;
        hmma64(sb, 0, wm, wn, lr, lc, acc);
        hmma64(sb, 1, wm, wn, lr, lc, acc);
        hmma64(sb, 2, wm, wn, lr, lc, acc);
        hmma64(sb, 3, wm, wn, lr, lc, acc);
    }

    const int qr = lane >> 2, qc = (lane & 3) << 1;
#pragma unroll
    for (int mi = 0; mi < 4; mi++) {
#pragma unroll
        for (int ni = 0; ni < 4; ni++) {
            int rl = wm + mi * 16 + qr;
            int cl = wn + ni * 8 + qc;
            int k = k0 + cl;
            int qA = q0 + rl, qB = qA + 8;
            float2 v0 = { (k <= qA) ? acc[mi][ni][0] : NEG_INF,
                          (k + 1 <= qA) ? acc[mi][ni][1] : NEG_INF };
            float2 v1 = { (k <= qB) ? acc[mi][ni][2] : NEG_INF,
                          (k + 1 <= qB) ? acc[mi][ni][3] : NEG_INF };
            *(float2*)&P[pbase + (size_t)rl * SS + cl] = v0;
            *(float2*)&P[pbase + (size_t)(rl + 8) * SS + cl] = v1;
        }
    }
}

// ---------------------------------------------------------------------------
// pv_tc: AO = P @ V^T (fp16 1-product), causal k-bound. BK=64, 3-stage.
// ---------------------------------------------------------------------------
__global__ __launch_bounds__(256, 2) void pv_tc(
    const __half* __restrict__ Ph,
    const __half* __restrict__ Vth,
    __half* __restrict__ AOh)
{
    extern __shared__ char smem[];
    const uint32_t sbase = smem_u32(smem);
    const int t = threadIdx.x;
    const int wid = t >> 5, lane = t & 31;
    const int q0 = blockIdx.x << 7;
    const int bh = blockIdx.y;
    const int b = bh >> 5, h = bh & 31;

    const __half* base0 = Ph  + ((size_t)bh * SS + q0) * SS;
    const __half* base1 = Vth + (size_t)bh * HD * SS;

    const int iters = (q0 >> 6) + 2;   // kend/64, kend = q0+128

    load_stage64(sbase,       base0, base1, SS, 0,  t);
    load_stage64(sbase + STG, base0, base1, SS, 64, t);

    const int wm = (wid & 1) << 6;
    const int wn = (wid >> 1) << 5;
    const int lr = lane & 15, lc = lane >> 4;
    float acc[4][4][4] = {};

    for (int it = 0; it < iters; it++) {
        int stg = it % NST;
        CP_WAIT1();
        __syncthreads();
        uint32_t sb = sbase + stg * STG;
        hmma64(sb, 0, wm, wn, lr, lc, acc);
        hmma64(sb, 1, wm, wn, lr, lc, acc);
        hmma64(sb, 2, wm, wn, lr, lc, acc);
        hmma64(sb, 3, wm, wn, lr, lc, acc);
        int nx = it + 2;
        if (nx < iters) load_stage64(sbase + (nx % NST) * STG, base0, base1, SS, nx * 64, t);
        else CP_COMMIT();
    }

    const int qr = lane >> 2, qc = (lane & 3) << 1;
#pragma unroll
    for (int mi = 0; mi < 4; mi++) {
#pragma unroll
        for (int ni = 0; ni < 4; ni++) {
            int row = q0 + wm + mi * 16 + qr;
            int col = (h << 7) + wn + ni * 8 + qc;
            size_t m0 = ((size_t)b * SS + row) * DD + col;
            size_t m1 = m0 + (size_t)8 * DD;
            *(__half2*)&AOh[m0] = __halves2half2(__float2half_rn(acc[mi][ni][0]),
                                                 __float2half_rn(acc[mi][ni][1]));
            *(__half2*)&AOh[m1] = __halves2half2(__float2half_rn(acc[mi][ni][2]),
                                                 __float2half_rn(acc[mi][ni][3]));
        }
    }
}

// ---------------------------------------------------------------------------
// prep_hidden: hidden -> hh (fp16 hi) + qh (roped+scaled Q, fp16 hi)
// ---------------------------------------------------------------------------
__global__ void prep_hidden(const float* __restrict__ src,
                            __half* __restrict__ hh, __half* __restrict__ qh,
                            const float* __restrict__ cosp, const float* __restrict__ sinp,
                            float scale)
{
    int idx = blockIdx.x * blockDim.x + threadIdx.x;
    const int total = BB * SS * HH * (HD / 2);
    if (idx >= total) return;
    int d  = idx & 63;
    int h  = (idx >> 6) & (HH - 1);
    int bs = idx >> 11;
    size_t base = (size_t)bs * DD + (h << 7);
    size_t cbase = (size_t)bs * HD;
    float c0 = cosp[cbase + d],      s0 = sinp[cbase + d];
    float c1 = cosp[cbase + d + 64], s1 = sinp[cbase + d + 64];
    float x0 = src[base + d], x1 = src[base + d + 64];
    hh[base + d]      = __float2half_rn(x0);
    hh[base + d + 64] = __float2half_rn(x1);
    float y0 = (x0 * c0 - x1 * s0) * scale;
    float y1 = (x1 * c1 + x0 * s1) * scale;
    qh[base + d]      = __float2half_rn(y0);
    qh[base + d + 64] = __float2half_rn(y1);
}

// fp32 -> fp16 hi, 3 weight tensors in one launch (blockIdx.y selects)
__global__ void conv_hi3(const float* __restrict__ x0, __half* __restrict__ h0,
                         const float* __restrict__ x1, __half* __restrict__ h1,
                         const float* __restrict__ x2, __half* __restrict__ h2)
{
    size_t i = (size_t)blockIdx.x * blockDim.x + threadIdx.x;
    if (i >= NELT / 4) return;
    const float* x = (blockIdx.y == 0) ? x0 : (blockIdx.y == 1) ? x1 : x2;
    __half* hi = (blockIdx.y == 0) ? h0 : (blockIdx.y == 1) ? h1 : h2;
    float4 v = ((const float4*)x)[i];
    ((__half2*)hi)[i * 2]     = __halves2half2(__float2half_rn(v.x), __float2half_rn(v.y));
    ((__half2*)hi)[i * 2 + 1] = __halves2half2(__float2half_rn(v.z), __float2half_rn(v.w));
}

// ---------------------------------------------------------------------------
// Causal softmax + fp16 emission. Reads/writes only the causal region
// (cols >= kend already zeroed by score's masked blocks).
// ---------------------------------------------------------------------------
__global__ __launch_bounds__(256) void softmax_pconv_kernel(
    float* __restrict__ P, __half* __restrict__ Ph)
{
    size_t row = blockIdx.x;
    int q = (int)(row & (SS - 1));
    int kend = ((q >> 7) + 1) << 7;
    float4* p4 = (float4*)(P + row * (size_t)SS);
    __half* ph = Ph + row * (size_t)SS;
    int t = threadIdx.x;

    float v[8];
    {
        float4 va = p4[t];
        int oa = t << 2;
        v[0] = (oa     <= q) ? va.x : -3.4e38f;
        v[1] = (oa + 1 <= q) ? va.y : -3.4e38f;
        v[2] = (oa + 2 <= q) ? va.z : -3.4e38f;
        v[3] = (oa + 3 <= q) ? va.w : -3.4e38f;
        if (kend > 1024) {
            float4 vb = p4[t + 256];
            int ob = 1024 + (t << 2);
            v[4] = (ob     <= q) ? vb.x : -3.4e38f;
            v[5] = (ob + 1 <= q) ? vb.y : -3.4e38f;
            v[6] = (ob + 2 <= q) ? vb.z : -3.4e38f;
            v[7] = (ob + 3 <= q) ? vb.w : -3.4e38f;
        } else {
            v[4] = v[5] = v[6] = v[7] = -3.4e38f;
        }
    }
    float mx = v[0];
#pragma unroll
    for (int i = 1; i < 8; i++) mx = fmaxf(mx, v[i]);
#pragma unroll
    for (int o = 16; o; o >>= 1) mx = fmaxf(mx, __shfl_xor_sync(0xffffffffu, mx, o));
    __shared__ float rmax[8], rsum[8];
    if ((t & 31) == 0) rmax[t >> 5] = mx;
    __syncthreads();
    mx = rmax[0];
#pragma unroll
    for (int i = 1; i < 8; i++) mx = fmaxf(mx, rmax[i]);
    float sum = 0.f;
#pragma unroll
    for (int i = 0; i < 8; i++) {
        v[i] = (v[i] > -3.3e38f) ? __expf(v[i] - mx) : 0.f;
        sum += v[i];
    }
#pragma unroll
    for (int o = 16; o; o >>= 1) sum += __shfl_xor_sync(0xffffffffu, sum, o);
    if ((t & 31) == 0) rsum[t >> 5] = sum;
    __syncthreads();
    sum = rsum[0];
#pragma unroll
    for (int i = 1; i < 8; i++) sum += rsum[i];
    float inv = 1.0f / sum;
#pragma unroll
    for (int i = 0; i < 8; i++) v[i] *= inv;

    {
        int oa = t << 2;
        if (oa < kend) {
            p4[t] = make_float4(v[0], v[1], v[2], v[3]);
            *(__half2*)&ph[oa]     = __halves2half2(__float2half_rn(v[0]), __float2half_rn(v[1]));
            *(__half2*)&ph[oa + 2] = __halves2half2(__float2half_rn(v[2]), __float2half_rn(v[3]));
        }
        int ob = 1024 + (t << 2);
        if (ob < kend) {
            p4[t + 256] = make_float4(v[4], v[5], v[6], v[7]);
            *(__half2*)&ph[ob]     = __halves2half2(__float2half_rn(v[4]), __float2half_rn(v[5]));
            *(__half2*)&ph[ob + 2] = __halves2half2(__float2half_rn(v[6]), __float2half_rn(v[7]));
        }
    }
}

// ---------------------------------------------------------------------------
extern "C" void kernel_launch(void* const* d_in, const int* in_sizes, int n_in,
                              void* d_out, int out_size)
{
    (void)in_sizes; (void)n_in; (void)out_size;
    const float* hidden = (const float*)d_in[0];
    const float* Wqk    = (const float*)d_in[1];
    const float* bqk    = (const float*)d_in[2];
    const float* Wv     = (const float*)d_in[3];
    const float* bv     = (const float*)d_in[4];
    const float* Wo     = (const float*)d_in[5];
    const float* cosp   = (const float*)d_in[6];
    const float* sinp   = (const float*)d_in[7];

    float* out   = (float*)d_out;
    float* attnw = out + (size_t)BB * SS * DD;

    __half *hh, *qkh, *vh, *oh, *qh, *kh, *vth, *aoh, *ph;
    cudaGetSymbolAddress((void**)&hh,  g_hh);
    cudaGetSymbolAddress((void**)&qkh, g_qkh);
    cudaGetSymbolAddress((void**)&vh,  g_vh);
    cudaGetSymbolAddress((void**)&oh,  g_oh);
    cudaGetSymbolAddress((void**)&qh,  g_qh);
    cudaGetSymbolAddress((void**)&kh,  g_kh);
    cudaGetSymbolAddress((void**)&vth, g_vth);
    cudaGetSymbolAddress((void**)&aoh, g_aoh);
    cudaGetSymbolAddress((void**)&ph,  g_ph);

    cudaFuncSetAttribute(gemm_qkv_tc, cudaFuncAttributeMaxDynamicSharedMemorySize, SMEM_P);
    cudaFuncSetAttribute(gemm1_tc,    cudaFuncAttributeMaxDynamicSharedMemorySize, SMEM_P);
    cudaFuncSetAttribute(score_tc,    cudaFuncAttributeMaxDynamicSharedMemorySize, SMEM_S);
    cudaFuncSetAttribute(pv_tc,       cudaFuncAttributeMaxDynamicSharedMemorySize, SMEM_P);

    const int cvblk = (int)((NELT / 4 + 255) / 256);
    const int rope_total = BB * SS * HH * (HD / 2);
    const float scale = 0.088388347648318447f;  // 128^-0.5

    prep_hidden<<<(rope_total + 255) / 256, 256>>>(hidden, hh, qh, cosp, sinp, scale);
    conv_hi3<<<dim3(cvblk, 3), 256>>>(Wqk, qkh, Wv, vh, Wo, oh);

    // fused QK + V projections in one launch (tail waves merged)
    gemm_qkv_tc<<<dim3(DD / 128, (BB * SS) / 128, 2), 256, SMEM_P>>>(
        hh, qkh, vh, bqk, bv, cosp, sinp, kh, vth);

    score_tc<<<dim3(SS / 128, SS / 128, BB * HH), 256, SMEM_S>>>(qh, kh, attnw);
    softmax_pconv_kernel<<<BB * HH * SS, 256>>>(attnw, ph);
    pv_tc<<<dim3(SS / 128, BB * HH), 256, SMEM_P>>>(ph, vth, aoh);

    // final projection (1-product)
    gemm1_tc<<<dim3(DD / 128, (BB * SS) / 128), 256, SMEM_P>>>(aoh, oh, out);
}